// round 3
// baseline (speedup 1.0000x reference)
#include <cuda_runtime.h>
#include <math.h>

#define NTOK 1024
#define DIMV 512
#define HIDV 2048
#define NEXP 64
#define KSPL 4

// ---------------- scratch (device globals; no allocation allowed) ----------
__device__ float g_h[NTOK * HIDV];               // hidden after GELU (8 MB)
__device__ float g_part[KSPL * NTOK * DIMV];     // FC2 K-split partials (8 MB)
__device__ int   g_idx[2][NTOK];
__device__ float g_gate[2][NTOK];
__device__ int   g_cnt[2][NEXP];
__device__ int   g_off[2][NEXP];
__device__ int   g_list[2][NTOK];

// ---------------- packed f32x2 FMA (Blackwell) ------------------------------
__device__ __forceinline__ float2 ffma2(float2 a, float2 b, float2 c) {
    float2 d;
    asm("fma.rn.f32x2 %0, %1, %2, %3;"
        : "=l"(*reinterpret_cast<unsigned long long*>(&d))
        : "l"(*reinterpret_cast<const unsigned long long*>(&a)),
          "l"(*reinterpret_cast<const unsigned long long*>(&b)),
          "l"(*reinterpret_cast<const unsigned long long*>(&c)));
    return d;
}

__device__ __forceinline__ float gelu_f(float v) {
    return 0.5f * v * (1.0f + erff(v * 0.70710678118654752440f));
}

// ---------------- reset per-launch counters ---------------------------------
__global__ void zero_kernel() {
    int t = threadIdx.x;
    if (t < NEXP) { g_cnt[0][t] = 0; g_cnt[1][t] = 0; }
}

// ---------------- top-1 gating -----------------------------------------------
// grid = NTOK/8 blocks, 64 threads (one expert per thread), 8 tokens per block.
// emb row is streamed per-thread (read once per block from L2); x reads are
// warp-uniform broadcasts (L1 hits).
template<int DIN>
__global__ void gate_kernel(const float* __restrict__ X,
                            const float* __restrict__ EMB,
                            float scale, int layer) {
    const int e = threadIdx.x;          // 0..63
    const int t0 = blockIdx.x * 8;
    const float* er = EMB + (size_t)e * DIN;

    float2 acc[8];
    #pragma unroll
    for (int t = 0; t < 8; t++) acc[t] = make_float2(0.f, 0.f);

    #pragma unroll 2
    for (int k4 = 0; k4 < DIN / 4; k4++) {
        float4 w = *(const float4*)(er + k4 * 4);
        float2 w01 = make_float2(w.x, w.y);
        float2 w23 = make_float2(w.z, w.w);
        #pragma unroll
        for (int t = 0; t < 8; t++) {
            float4 xv = *(const float4*)(X + (size_t)(t0 + t) * DIN + k4 * 4);
            acc[t] = ffma2(make_float2(xv.x, xv.y), w01, acc[t]);
            acc[t] = ffma2(make_float2(xv.z, xv.w), w23, acc[t]);
        }
    }

    __shared__ float s_logit[8][NEXP];
    #pragma unroll
    for (int t = 0; t < 8; t++) s_logit[t][e] = (acc[t].x + acc[t].y) * scale;
    __syncthreads();

    if (threadIdx.x < 8) {
        const int t = threadIdx.x;
        float m = s_logit[t][0]; int mi = 0;
        for (int i = 1; i < NEXP; i++)
            if (s_logit[t][i] > m) { m = s_logit[t][i]; mi = i; }
        float s = 0.f;
        for (int i = 0; i < NEXP; i++) s += expf(s_logit[t][i] - m);
        g_idx[layer][t0 + t]  = mi;
        g_gate[layer][t0 + t] = 1.0f / s;   // max softmax prob
        atomicAdd(&g_cnt[layer][mi], 1);
    }
}

// ---------------- build per-expert token lists ------------------------------
__global__ void group_kernel(int layer) {
    __shared__ int s_cur[NEXP];
    if (threadIdx.x == 0) {
        int a = 0;
        for (int e = 0; e < NEXP; e++) {
            g_off[layer][e] = a;
            s_cur[e] = a;
            a += g_cnt[layer][e];
        }
    }
    __syncthreads();
    for (int i = threadIdx.x; i < NTOK; i += blockDim.x) {
        int e = g_idx[layer][i];
        int p = atomicAdd(&s_cur[e], 1);
        g_list[layer][p] = i;
    }
}

// ---------------- grouped expert FC (pipelined) ------------------------------
// grid = (DOUT/128, NEXP, DIN/512); 128 threads.
// Warp w handles tokens 4w..4w+3 of the 16-token tile; lane l owns 4 columns.
// Inner k-loop processes 4 k-rows per step with a register double buffer:
// next 4 W rows (4 x LDG.128) are issued before computing the current 4.
template<int DIN, int DOUT, bool GELU, bool EPI>
__global__ void __launch_bounds__(128, 6)
fc_kernel(const float* __restrict__ X,
          const float* __restrict__ W,
          const float* __restrict__ Bv,
          int layer,
          float* __restrict__ OUT) {
    const int e = blockIdx.y;
    const int m = g_cnt[layer][e];
    if (m == 0) return;

    const int lane = threadIdx.x & 31;
    const int wg = threadIdx.x >> 5;                 // warp id 0..3
    const int colBase = blockIdx.x * 128 + lane * 4;
    const int k0 = blockIdx.z * 512;

    __shared__ float s_x[16][512];
    __shared__ int s_row[16];

    const int base = g_off[layer][e];
    const float* Wb = W + (size_t)e * DIN * DOUT + (size_t)k0 * DOUT + colBase;
    const float* gatep = g_gate[layer];

    float4 bl;
    if (EPI) bl = *(const float4*)(Bv + (size_t)e * DOUT + colBase);

    for (int t0 = 0; t0 < m; t0 += 16) {
        __syncthreads();   // previous tile's readers done
        if (threadIdx.x < 16)
            s_row[threadIdx.x] = (t0 + threadIdx.x < m)
                                 ? g_list[layer][base + t0 + threadIdx.x] : -1;
        __syncthreads();

        // stage 16 x 512 chunk of X (float4, coalesced)
        #pragma unroll 4
        for (int i = threadIdx.x; i < 16 * 128; i += 128) {
            int t = i >> 7, k4 = i & 127;
            int r = s_row[t];
            float4 v = (r >= 0)
                ? *(const float4*)(X + (size_t)r * DIN + k0 + k4 * 4)
                : make_float4(0.f, 0.f, 0.f, 0.f);
            *(float4*)&s_x[t][k4 * 4] = v;
        }
        __syncthreads();

        float2 acc[4][2];
        #pragma unroll
        for (int j = 0; j < 4; j++) {
            acc[j][0] = make_float2(0.f, 0.f);
            acc[j][1] = make_float2(0.f, 0.f);
        }

        // ---- pipelined k loop: 4 rows per step, double-buffered W ----
        float4 wc[4];
        #pragma unroll
        for (int u = 0; u < 4; u++)
            wc[u] = *(const float4*)(Wb + (size_t)u * DOUT);

        #pragma unroll 1
        for (int k = 0; k < 512; k += 4) {
            const int kn = (k + 4 < 512) ? (k + 4) : k;   // clamp: last prefetch re-reads
            float4 wn[4];
            #pragma unroll
            for (int u = 0; u < 4; u++)
                wn[u] = *(const float4*)(Wb + (size_t)(kn + u) * DOUT);

            #pragma unroll
            for (int j = 0; j < 4; j++) {
                float4 xv = *(const float4*)&s_x[wg * 4 + j][k];  // broadcast LDS.128
                acc[j][0] = ffma2(make_float2(xv.x, xv.x), make_float2(wc[0].x, wc[0].y), acc[j][0]);
                acc[j][1] = ffma2(make_float2(xv.x, xv.x), make_float2(wc[0].z, wc[0].w), acc[j][1]);
                acc[j][0] = ffma2(make_float2(xv.y, xv.y), make_float2(wc[1].x, wc[1].y), acc[j][0]);
                acc[j][1] = ffma2(make_float2(xv.y, xv.y), make_float2(wc[1].z, wc[1].w), acc[j][1]);
                acc[j][0] = ffma2(make_float2(xv.z, xv.z), make_float2(wc[2].x, wc[2].y), acc[j][0]);
                acc[j][1] = ffma2(make_float2(xv.z, xv.z), make_float2(wc[2].z, wc[2].w), acc[j][1]);
                acc[j][0] = ffma2(make_float2(xv.w, xv.w), make_float2(wc[3].x, wc[3].y), acc[j][0]);
                acc[j][1] = ffma2(make_float2(xv.w, xv.w), make_float2(wc[3].z, wc[3].w), acc[j][1]);
            }
            #pragma unroll
            for (int u = 0; u < 4; u++) wc[u] = wn[u];
        }

        // epilogue
        #pragma unroll
        for (int j = 0; j < 4; j++) {
            int r = s_row[wg * 4 + j];
            if (r < 0) continue;
            if (EPI) {
                float g = gatep[r];
                float v0 = (acc[j][0].x + bl.x) * g;
                float v1 = (acc[j][0].y + bl.y) * g;
                float v2 = (acc[j][1].x + bl.z) * g;
                float v3 = (acc[j][1].y + bl.w) * g;
                if (GELU) {
                    v0 = gelu_f(v0); v1 = gelu_f(v1);
                    v2 = gelu_f(v2); v3 = gelu_f(v3);
                }
                *(float4*)(OUT + (size_t)r * DOUT + colBase) =
                    make_float4(v0, v1, v2, v3);
            } else {
                // raw partial sums; combine kernel applies bias/gate
                *(float4*)(OUT + ((size_t)blockIdx.z * NTOK + r) * DOUT + colBase) =
                    make_float4(acc[j][0].x, acc[j][0].y, acc[j][1].x, acc[j][1].y);
            }
        }
    }
}

// ---------------- FC2 K-split combine + bias + gate --------------------------
// grid = NTOK blocks, 128 threads; each thread does one float4 (512 cols)
__global__ void epi2_kernel(const float* __restrict__ B2v,
                            float* __restrict__ OUT) {
    const int t = blockIdx.x;
    const int c = threadIdx.x * 4;
    const int e = g_idx[1][t];
    const float g = g_gate[1][t];
    float4 s = *(const float4*)(B2v + (size_t)e * DIMV + c);
    #pragma unroll
    for (int z = 0; z < KSPL; z++) {
        float4 p = *(const float4*)&g_part[((size_t)z * NTOK + t) * DIMV + c];
        s.x += p.x; s.y += p.y; s.z += p.z; s.w += p.w;
    }
    *(float4*)(OUT + (size_t)t * DIMV + c) =
        make_float4(s.x * g, s.y * g, s.z * g, s.w * g);
}

// ---------------- launch ------------------------------------------------------
extern "C" void kernel_launch(void* const* d_in, const int* in_sizes, int n_in,
                              void* d_out, int out_size) {
    const float* x    = (const float*)d_in[0];
    const float* emb1 = (const float*)d_in[1];
    const float* W1   = (const float*)d_in[2];
    const float* b1   = (const float*)d_in[3];
    const float* emb2 = (const float*)d_in[4];
    const float* W2   = (const float*)d_in[5];
    const float* b2   = (const float*)d_in[6];
    float* out = (float*)d_out;

    void* hp = nullptr;
    cudaGetSymbolAddress(&hp, g_h);
    float* h = (float*)hp;
    void* pp = nullptr;
    cudaGetSymbolAddress(&pp, g_part);
    float* part = (float*)pp;

    const float scale1 = 0.044194173824159216f;   // 1/sqrt(512)
    const float scale2 = 0.022097086912079612f;   // 1/sqrt(2048)

    zero_kernel<<<1, 64>>>();

    gate_kernel<DIMV><<<NTOK / 8, 64>>>(x, emb1, scale1, 0);
    group_kernel<<<1, 256>>>(0);
    // FC1: K=512 single pass, fused epilogue (gelu + gate)
    fc_kernel<DIMV, HIDV, true, true>
        <<<dim3(HIDV / 128, NEXP, 1), 128>>>(x, W1, b1, 0, h);

    gate_kernel<HIDV><<<NTOK / 8, 64>>>(h, emb2, scale2, 1);
    group_kernel<<<1, 256>>>(1);
    // FC2: K=2048 split in 4 (grid.z), partials to g_part, then combine
    fc_kernel<HIDV, DIMV, false, false>
        <<<dim3(DIMV / 128, NEXP, KSPL), 128>>>(h, W2, b2, 1, part);
    epi2_kernel<<<NTOK, 128>>>(b2, out);
}

// round 4
// speedup vs baseline: 1.6315x; 1.6315x over previous
#include <cuda_runtime.h>
#include <math.h>

#define NTOK 1024
#define DIMV 512
#define HIDV 2048
#define NEXP 64

// ---------------- scratch (device globals; no allocation allowed) ----------
__device__ float g_h[NTOK * HIDV];            // hidden after GELU (8 MB)
__device__ float g_part[2 * NTOK * HIDV];     // K-split partials (16 MB, shared by FC1/FC2)
__device__ int   g_idx[2][NTOK];
__device__ float g_gate[2][NTOK];
__device__ int   g_cnt[2][NEXP];
__device__ int   g_off[2][NEXP];
__device__ int   g_list[2][NTOK];

// ---------------- packed f32x2 FMA (Blackwell) ------------------------------
__device__ __forceinline__ float2 ffma2(float2 a, float2 b, float2 c) {
    float2 d;
    asm("fma.rn.f32x2 %0, %1, %2, %3;"
        : "=l"(*reinterpret_cast<unsigned long long*>(&d))
        : "l"(*reinterpret_cast<const unsigned long long*>(&a)),
          "l"(*reinterpret_cast<const unsigned long long*>(&b)),
          "l"(*reinterpret_cast<const unsigned long long*>(&c)));
    return d;
}

__device__ __forceinline__ float gelu_f(float v) {
    return 0.5f * v * (1.0f + erff(v * 0.70710678118654752440f));
}

// ---------------- reset per-launch counters ---------------------------------
__global__ void zero_kernel() {
    int t = threadIdx.x;
    if (t < NEXP) { g_cnt[0][t] = 0; g_cnt[1][t] = 0; }
}

// ---------------- top-1 gating -----------------------------------------------
// grid = NTOK/8 blocks, 64 threads (one expert per thread), 8 tokens per block.
template<int DIN>
__global__ void gate_kernel(const float* __restrict__ X,
                            const float* __restrict__ EMB,
                            float scale, int layer) {
    const int e = threadIdx.x;          // 0..63
    const int t0 = blockIdx.x * 8;
    const float* er = EMB + (size_t)e * DIN;

    float2 acc[8];
    #pragma unroll
    for (int t = 0; t < 8; t++) acc[t] = make_float2(0.f, 0.f);

    #pragma unroll 2
    for (int k4 = 0; k4 < DIN / 4; k4++) {
        float4 w = *(const float4*)(er + k4 * 4);
        float2 w01 = make_float2(w.x, w.y);
        float2 w23 = make_float2(w.z, w.w);
        #pragma unroll
        for (int t = 0; t < 8; t++) {
            float4 xv = *(const float4*)(X + (size_t)(t0 + t) * DIN + k4 * 4);
            acc[t] = ffma2(make_float2(xv.x, xv.y), w01, acc[t]);
            acc[t] = ffma2(make_float2(xv.z, xv.w), w23, acc[t]);
        }
    }

    __shared__ float s_logit[8][NEXP];
    #pragma unroll
    for (int t = 0; t < 8; t++) s_logit[t][e] = (acc[t].x + acc[t].y) * scale;
    __syncthreads();

    if (threadIdx.x < 8) {
        const int t = threadIdx.x;
        float m = s_logit[t][0]; int mi = 0;
        for (int i = 1; i < NEXP; i++)
            if (s_logit[t][i] > m) { m = s_logit[t][i]; mi = i; }
        float s = 0.f;
        for (int i = 0; i < NEXP; i++) s += expf(s_logit[t][i] - m);
        g_idx[layer][t0 + t]  = mi;
        g_gate[layer][t0 + t] = 1.0f / s;   // max softmax prob
        atomicAdd(&g_cnt[layer][mi], 1);
    }
}

// ---------------- build per-expert token lists ------------------------------
__global__ void group_kernel(int layer) {
    __shared__ int s_cur[NEXP];
    if (threadIdx.x == 0) {
        int a = 0;
        for (int e = 0; e < NEXP; e++) {
            g_off[layer][e] = a;
            s_cur[e] = a;
            a += g_cnt[layer][e];
        }
    }
    __syncthreads();
    for (int i = threadIdx.x; i < NTOK; i += blockDim.x) {
        int e = g_idx[layer][i];
        int p = atomicAdd(&s_cur[e], 1);
        g_list[layer][p] = i;
    }
}

// ---------------- grouped expert FC (warp = 64 distinct cols x 16 tokens) ----
// grid = (DOUT/256, NEXP, DIN/KLEN); 128 threads.
// Warp wg owns cols [blk*256 + wg*64, +64); lane owns 2 cols (LDG.64 W rows).
// Each warp processes ALL 16 tokens of the tile -> each W load feeds 16 tokens
// worth of FMA (register reuse), and warps load DISTINCT W (no L1 redundancy).
// Writes raw partial sums; epilogue kernels apply bias/gate/gelu.
template<int DIN, int DOUT, int KLEN>
__global__ void __launch_bounds__(128, 5)
fc_kernel(const float* __restrict__ X,
          const float* __restrict__ W,
          int layer,
          float* __restrict__ OUT) {
    const int e = blockIdx.y;
    const int m = g_cnt[layer][e];
    if (m == 0) return;

    const int lane = threadIdx.x & 31;
    const int wg = threadIdx.x >> 5;
    const int colBase = blockIdx.x * 256 + wg * 64 + lane * 2;
    const int k0 = blockIdx.z * KLEN;

    __shared__ float s_x[16][KLEN];
    __shared__ int s_row[16];

    const int base = g_off[layer][e];
    const float* Wb = W + (size_t)e * DIN * DOUT + (size_t)k0 * DOUT + colBase;

    constexpr int K4 = KLEN / 4;

    for (int t0 = 0; t0 < m; t0 += 16) {
        __syncthreads();   // previous tile fully consumed
        if (threadIdx.x < 16)
            s_row[threadIdx.x] = (t0 + threadIdx.x < m)
                                 ? g_list[layer][base + t0 + threadIdx.x] : -1;
        __syncthreads();

        // stage 16 x KLEN chunk of X (float4, coalesced)
        #pragma unroll
        for (int i = threadIdx.x; i < 16 * K4; i += 128) {
            int t = i / K4, k4 = i % K4;
            int r = s_row[t];
            float4 v = (r >= 0)
                ? *(const float4*)(X + (size_t)r * DIN + k0 + k4 * 4)
                : make_float4(0.f, 0.f, 0.f, 0.f);
            *(float4*)&s_x[t][k4 * 4] = v;
        }
        __syncthreads();

        float2 acc[16];
        #pragma unroll
        for (int j = 0; j < 16; j++) acc[j] = make_float2(0.f, 0.f);

        // ---- k loop: 16 rows per iter, two 8-row batches, double-buffered ----
        float2 wb0[8], wb1[8];
        const float* wpk = Wb;
        #pragma unroll
        for (int u = 0; u < 8; u++)
            wb0[u] = *(const float2*)(wpk + (size_t)u * DOUT);

        #pragma unroll 1
        for (int kb = 0; kb < KLEN; kb += 16) {
            #pragma unroll
            for (int u = 0; u < 8; u++)
                wb1[u] = *(const float2*)(wpk + (size_t)(8 + u) * DOUT);

            #pragma unroll
            for (int j = 0; j < 16; j++) {
                float4 xa = *(const float4*)&s_x[j][kb];
                float4 xb = *(const float4*)&s_x[j][kb + 4];
                acc[j] = ffma2(make_float2(xa.x, xa.x), wb0[0], acc[j]);
                acc[j] = ffma2(make_float2(xa.y, xa.y), wb0[1], acc[j]);
                acc[j] = ffma2(make_float2(xa.z, xa.z), wb0[2], acc[j]);
                acc[j] = ffma2(make_float2(xa.w, xa.w), wb0[3], acc[j]);
                acc[j] = ffma2(make_float2(xb.x, xb.x), wb0[4], acc[j]);
                acc[j] = ffma2(make_float2(xb.y, xb.y), wb0[5], acc[j]);
                acc[j] = ffma2(make_float2(xb.z, xb.z), wb0[6], acc[j]);
                acc[j] = ffma2(make_float2(xb.w, xb.w), wb0[7], acc[j]);
            }

            if (kb + 16 < KLEN) {
                #pragma unroll
                for (int u = 0; u < 8; u++)
                    wb0[u] = *(const float2*)(wpk + (size_t)(16 + u) * DOUT);
            }

            #pragma unroll
            for (int j = 0; j < 16; j++) {
                float4 xa = *(const float4*)&s_x[j][kb + 8];
                float4 xb = *(const float4*)&s_x[j][kb + 12];
                acc[j] = ffma2(make_float2(xa.x, xa.x), wb1[0], acc[j]);
                acc[j] = ffma2(make_float2(xa.y, xa.y), wb1[1], acc[j]);
                acc[j] = ffma2(make_float2(xa.z, xa.z), wb1[2], acc[j]);
                acc[j] = ffma2(make_float2(xa.w, xa.w), wb1[3], acc[j]);
                acc[j] = ffma2(make_float2(xb.x, xb.x), wb1[4], acc[j]);
                acc[j] = ffma2(make_float2(xb.y, xb.y), wb1[5], acc[j]);
                acc[j] = ffma2(make_float2(xb.z, xb.z), wb1[6], acc[j]);
                acc[j] = ffma2(make_float2(xb.w, xb.w), wb1[7], acc[j]);
            }
            wpk += (size_t)16 * DOUT;
        }

        // write raw partial sums (per-split slab)
        #pragma unroll
        for (int j = 0; j < 16; j++) {
            int r = s_row[j];
            if (r < 0) continue;
            *(float2*)(OUT + ((size_t)blockIdx.z * NTOK + r) * DOUT + colBase) = acc[j];
        }
    }
}

// ---------------- FC1 combine: bias + gate + gelu -> h -----------------------
// grid = NTOK blocks, 512 threads (2048 cols / float4)
__global__ void epi1_kernel(const float* __restrict__ B1v,
                            float* __restrict__ H) {
    const int t = blockIdx.x;
    const int c = threadIdx.x * 4;
    const int e = g_idx[0][t];
    const float g = g_gate[0][t];
    float4 s = *(const float4*)(B1v + (size_t)e * HIDV + c);
    #pragma unroll
    for (int z = 0; z < 2; z++) {
        float4 p = *(const float4*)&g_part[((size_t)z * NTOK + t) * HIDV + c];
        s.x += p.x; s.y += p.y; s.z += p.z; s.w += p.w;
    }
    *(float4*)(H + (size_t)t * HIDV + c) =
        make_float4(gelu_f(s.x * g), gelu_f(s.y * g),
                    gelu_f(s.z * g), gelu_f(s.w * g));
}

// ---------------- FC2 combine: bias + gate -> out ----------------------------
// grid = NTOK blocks, 128 threads (512 cols / float4)
__global__ void epi2_kernel(const float* __restrict__ B2v,
                            float* __restrict__ OUT) {
    const int t = blockIdx.x;
    const int c = threadIdx.x * 4;
    const int e = g_idx[1][t];
    const float g = g_gate[1][t];
    float4 s = *(const float4*)(B2v + (size_t)e * DIMV + c);
    #pragma unroll
    for (int z = 0; z < 8; z++) {
        float4 p = *(const float4*)&g_part[((size_t)z * NTOK + t) * DIMV + c];
        s.x += p.x; s.y += p.y; s.z += p.z; s.w += p.w;
    }
    *(float4*)(OUT + (size_t)t * DIMV + c) =
        make_float4(s.x * g, s.y * g, s.z * g, s.w * g);
}

// ---------------- launch ------------------------------------------------------
extern "C" void kernel_launch(void* const* d_in, const int* in_sizes, int n_in,
                              void* d_out, int out_size) {
    const float* x    = (const float*)d_in[0];
    const float* emb1 = (const float*)d_in[1];
    const float* W1   = (const float*)d_in[2];
    const float* b1   = (const float*)d_in[3];
    const float* emb2 = (const float*)d_in[4];
    const float* W2   = (const float*)d_in[5];
    const float* b2   = (const float*)d_in[6];
    float* out = (float*)d_out;

    void* hp = nullptr;
    cudaGetSymbolAddress(&hp, g_h);
    float* h = (float*)hp;
    void* pp = nullptr;
    cudaGetSymbolAddress(&pp, g_part);
    float* part = (float*)pp;

    const float scale1 = 0.044194173824159216f;   // 1/sqrt(512)
    const float scale2 = 0.022097086912079612f;   // 1/sqrt(2048)

    zero_kernel<<<1, 64>>>();

    gate_kernel<DIMV><<<NTOK / 8, 64>>>(x, emb1, scale1, 0);
    group_kernel<<<1, 256>>>(0);
    // FC1: K=512 split x2 -> grid (2048/256, 64, 2) = 1024 CTAs
    fc_kernel<DIMV, HIDV, 256>
        <<<dim3(HIDV / 256, NEXP, 2), 128>>>(x, W1, 0, part);
    epi1_kernel<<<NTOK, 512>>>(b1, h);

    gate_kernel<HIDV><<<NTOK / 8, 64>>>(h, emb2, scale2, 1);
    group_kernel<<<1, 256>>>(1);
    // FC2: K=2048 split x8 -> grid (512/256, 64, 8) = 1024 CTAs
    fc_kernel<HIDV, DIMV, 256>
        <<<dim3(DIMV / 256, NEXP, 8), 128>>>(h, W2, 1, part);
    epi2_kernel<<<NTOK, 128>>>(b2, out);
}

// round 5
// speedup vs baseline: 1.7094x; 1.0477x over previous
#include <cuda_runtime.h>
#include <math.h>

#define NTOK 1024
#define DIMV 512
#define HIDV 2048
#define NEXP 64
#define MAXTILE 160

// ---------------- scratch (device globals; no allocation allowed) ----------
__device__ float g_h[NTOK * HIDV];            // hidden after GELU (8 MB)
__device__ float g_part[2 * NTOK * HIDV];     // K-split partials (16 MB shared)
__device__ int   g_idx[2][NTOK];
__device__ float g_gate[2][NTOK];
__device__ int   g_list[2][NTOK];
__device__ int   g_ntile[2];
__device__ int2  g_tiles[2][MAXTILE];         // x = e | (cnt<<16), y = abs base in g_list

// ---------------- packed f32x2 FMA (Blackwell) ------------------------------
__device__ __forceinline__ float2 ffma2(float2 a, float2 b, float2 c) {
    float2 d;
    asm("fma.rn.f32x2 %0, %1, %2, %3;"
        : "=l"(*reinterpret_cast<unsigned long long*>(&d))
        : "l"(*reinterpret_cast<const unsigned long long*>(&a)),
          "l"(*reinterpret_cast<const unsigned long long*>(&b)),
          "l"(*reinterpret_cast<const unsigned long long*>(&c)));
    return d;
}

__device__ __forceinline__ float gelu_f(float v) {
    return 0.5f * v * (1.0f + erff(v * 0.70710678118654752440f));
}

// ---------------- top-1 gating (no atomics) ----------------------------------
// grid = NTOK/8 blocks, 64 threads (one expert per thread), 8 tokens per block.
template<int DIN>
__global__ void gate_kernel(const float* __restrict__ X,
                            const float* __restrict__ EMB,
                            float scale, int layer) {
    const int e = threadIdx.x;          // 0..63
    const int t0 = blockIdx.x * 8;
    const float* er = EMB + (size_t)e * DIN;

    float2 acc[8];
    #pragma unroll
    for (int t = 0; t < 8; t++) acc[t] = make_float2(0.f, 0.f);

    #pragma unroll 2
    for (int k4 = 0; k4 < DIN / 4; k4++) {
        float4 w = *(const float4*)(er + k4 * 4);
        float2 w01 = make_float2(w.x, w.y);
        float2 w23 = make_float2(w.z, w.w);
        #pragma unroll
        for (int t = 0; t < 8; t++) {
            float4 xv = *(const float4*)(X + (size_t)(t0 + t) * DIN + k4 * 4);
            acc[t] = ffma2(make_float2(xv.x, xv.y), w01, acc[t]);
            acc[t] = ffma2(make_float2(xv.z, xv.w), w23, acc[t]);
        }
    }

    __shared__ float s_logit[8][NEXP];
    #pragma unroll
    for (int t = 0; t < 8; t++) s_logit[t][e] = (acc[t].x + acc[t].y) * scale;
    __syncthreads();

    if (threadIdx.x < 8) {
        const int t = threadIdx.x;
        float m = s_logit[t][0]; int mi = 0;
        for (int i = 1; i < NEXP; i++)
            if (s_logit[t][i] > m) { m = s_logit[t][i]; mi = i; }
        float s = 0.f;
        for (int i = 0; i < NEXP; i++) s += expf(s_logit[t][i] - m);
        g_idx[layer][t0 + t]  = mi;
        g_gate[layer][t0 + t] = 1.0f / s;   // max softmax prob
    }
}

// ---------------- group: histogram + prefix + scatter + tile list ------------
__global__ void group_kernel(int layer) {
    __shared__ int s_cnt[NEXP], s_cur[NEXP];
    const int t = threadIdx.x;
    if (t < NEXP) s_cnt[t] = 0;
    __syncthreads();
    for (int i = t; i < NTOK; i += blockDim.x)
        atomicAdd(&s_cnt[g_idx[layer][i]], 1);
    __syncthreads();
    if (t == 0) {
        int a = 0, nt = 0;
        for (int e = 0; e < NEXP; e++) {
            s_cur[e] = a;
            const int c = s_cnt[e];
            for (int t0 = 0; t0 < c; t0 += 16) {
                int cnt = (c - t0 < 16) ? (c - t0) : 16;
                g_tiles[layer][nt++] = make_int2(e | (cnt << 16), a + t0);
            }
            a += c;
        }
        g_ntile[layer] = nt;
    }
    __syncthreads();
    for (int i = t; i < NTOK; i += blockDim.x) {
        int e = g_idx[layer][i];
        int p = atomicAdd(&s_cur[e], 1);
        g_list[layer][p] = i;
    }
}

// ---------------- grouped expert FC: one 16-token tile per CTA ---------------
// grid = (DOUT/256, MAXSLOT, DIN/KLEN); 128 threads.
// Warp wg owns cols [blk*256 + wg*64, +64); lane owns 2 cols (LDG.64 W rows).
// Warp processes all 16 tokens -> each W load feeds 16 FFMA2; warps load
// DISTINCT W (no L1 redundancy). Single-buffered 8-row W batches; latency
// hidden via occupancy (6 CTAs/SM). Raw partial sums out.
template<int DIN, int DOUT, int KLEN>
__global__ void __launch_bounds__(128, 6)
fc_kernel(const float* __restrict__ X,
          const float* __restrict__ W,
          int layer,
          float* __restrict__ OUT) {
    const int slot = blockIdx.y;
    if (slot >= g_ntile[layer]) return;
    const int2 tile = g_tiles[layer][slot];
    const int e = tile.x & 0xFFFF;
    const int cnt = tile.x >> 16;
    const int tbase = tile.y;

    const int lane = threadIdx.x & 31;
    const int wg = threadIdx.x >> 5;
    const int colBase = blockIdx.x * 256 + wg * 64 + lane * 2;
    const int k0 = blockIdx.z * KLEN;

    __shared__ float s_x[16][KLEN];
    __shared__ int s_row[16];

    const float* Wb = W + (size_t)e * DIN * DOUT + (size_t)k0 * DOUT + colBase;

    // issue first W batch early (hides under X staging)
    float2 wb[8];
    #pragma unroll
    for (int u = 0; u < 8; u++)
        wb[u] = *(const float2*)(Wb + (size_t)u * DOUT);

    if (threadIdx.x < 16)
        s_row[threadIdx.x] = (threadIdx.x < cnt)
                             ? g_list[layer][tbase + threadIdx.x] : -1;
    __syncthreads();

    // stage 16 x KLEN chunk of X (float4, coalesced)
    constexpr int K4 = KLEN / 4;
    #pragma unroll
    for (int i = threadIdx.x; i < 16 * K4; i += 128) {
        int t = i / K4, k4 = i % K4;
        int r = s_row[t];
        float4 v = (r >= 0)
            ? *(const float4*)(X + (size_t)r * DIN + k0 + k4 * 4)
            : make_float4(0.f, 0.f, 0.f, 0.f);
        *(float4*)&s_x[t][k4 * 4] = v;
    }
    __syncthreads();

    float2 acc[16];
    #pragma unroll
    for (int j = 0; j < 16; j++) acc[j] = make_float2(0.f, 0.f);

    #pragma unroll 1
    for (int kb = 0; kb < KLEN; kb += 8) {
        #pragma unroll
        for (int j = 0; j < 16; j++) {
            float4 xa = *(const float4*)&s_x[j][kb];      // broadcast LDS.128
            float4 xb = *(const float4*)&s_x[j][kb + 4];
            acc[j] = ffma2(make_float2(xa.x, xa.x), wb[0], acc[j]);
            acc[j] = ffma2(make_float2(xa.y, xa.y), wb[1], acc[j]);
            acc[j] = ffma2(make_float2(xa.z, xa.z), wb[2], acc[j]);
            acc[j] = ffma2(make_float2(xa.w, xa.w), wb[3], acc[j]);
            acc[j] = ffma2(make_float2(xb.x, xb.x), wb[4], acc[j]);
            acc[j] = ffma2(make_float2(xb.y, xb.y), wb[5], acc[j]);
            acc[j] = ffma2(make_float2(xb.z, xb.z), wb[6], acc[j]);
            acc[j] = ffma2(make_float2(xb.w, xb.w), wb[7], acc[j]);
        }
        if (kb + 8 < KLEN) {
            const float* wn = Wb + (size_t)(kb + 8) * DOUT;
            #pragma unroll
            for (int u = 0; u < 8; u++)
                wb[u] = *(const float2*)(wn + (size_t)u * DOUT);
        }
    }

    // write raw partial sums (per-split slab)
    #pragma unroll
    for (int j = 0; j < 16; j++) {
        int r = s_row[j];
        if (r < 0) continue;
        *(float2*)(OUT + ((size_t)blockIdx.z * NTOK + r) * DOUT + colBase) = acc[j];
    }
}

// ---------------- FC1 combine: bias + gate + gelu -> h -----------------------
__global__ void epi1_kernel(const float* __restrict__ B1v,
                            float* __restrict__ H) {
    const int t = blockIdx.x;
    const int c = threadIdx.x * 4;
    const int e = g_idx[0][t];
    const float g = g_gate[0][t];
    float4 s = *(const float4*)(B1v + (size_t)e * HIDV + c);
    #pragma unroll
    for (int z = 0; z < 2; z++) {
        float4 p = *(const float4*)&g_part[((size_t)z * NTOK + t) * HIDV + c];
        s.x += p.x; s.y += p.y; s.z += p.z; s.w += p.w;
    }
    *(float4*)(H + (size_t)t * HIDV + c) =
        make_float4(gelu_f(s.x * g), gelu_f(s.y * g),
                    gelu_f(s.z * g), gelu_f(s.w * g));
}

// ---------------- FC2 combine: bias + gate -> out ----------------------------
__global__ void epi2_kernel(const float* __restrict__ B2v,
                            float* __restrict__ OUT) {
    const int t = blockIdx.x;
    const int c = threadIdx.x * 4;
    const int e = g_idx[1][t];
    const float g = g_gate[1][t];
    float4 s = *(const float4*)(B2v + (size_t)e * DIMV + c);
    #pragma unroll
    for (int z = 0; z < 8; z++) {
        float4 p = *(const float4*)&g_part[((size_t)z * NTOK + t) * DIMV + c];
        s.x += p.x; s.y += p.y; s.z += p.z; s.w += p.w;
    }
    *(float4*)(OUT + (size_t)t * DIMV + c) =
        make_float4(s.x * g, s.y * g, s.z * g, s.w * g);
}

// ---------------- launch ------------------------------------------------------
extern "C" void kernel_launch(void* const* d_in, const int* in_sizes, int n_in,
                              void* d_out, int out_size) {
    const float* x    = (const float*)d_in[0];
    const float* emb1 = (const float*)d_in[1];
    const float* W1   = (const float*)d_in[2];
    const float* b1   = (const float*)d_in[3];
    const float* emb2 = (const float*)d_in[4];
    const float* W2   = (const float*)d_in[5];
    const float* b2   = (const float*)d_in[6];
    float* out = (float*)d_out;

    void* hp = nullptr;
    cudaGetSymbolAddress(&hp, g_h);
    float* h = (float*)hp;
    void* pp = nullptr;
    cudaGetSymbolAddress(&pp, g_part);
    float* part = (float*)pp;

    const float scale1 = 0.044194173824159216f;   // 1/sqrt(512)
    const float scale2 = 0.022097086912079612f;   // 1/sqrt(2048)

    gate_kernel<DIMV><<<NTOK / 8, 64>>>(x, emb1, scale1, 0);
    group_kernel<<<1, 256>>>(0);
    // FC1: K=512 split x2 (KLEN=256), one tile per CTA, 128 tile slots
    fc_kernel<DIMV, HIDV, 256>
        <<<dim3(HIDV / 256, 128, 2), 128>>>(x, W1, 0, part);
    epi1_kernel<<<NTOK, 512>>>(b1, h);

    gate_kernel<HIDV><<<NTOK / 8, 64>>>(h, emb2, scale2, 1);
    group_kernel<<<1, 256>>>(1);
    // FC2: K=2048 split x8 (KLEN=256), one tile per CTA
    fc_kernel<HIDV, DIMV, 256>
        <<<dim3(DIMV / 256, 128, 8), 128>>>(h, W2, 1, part);
    epi2_kernel<<<NTOK, 128>>>(b2, out);
}

// round 7
// speedup vs baseline: 2.2349x; 1.3074x over previous
#include <cuda_runtime.h>
#include <math.h>

#define NTOK 1024
#define DIMV 512
#define HIDV 2048
#define NEXP 64
#define MAXTILE 160

// ---------------- scratch (device globals; no allocation allowed) ----------
__device__ float g_h[NTOK * HIDV];            // hidden after GELU (8 MB)
__device__ float g_part[2 * NTOK * HIDV];     // K-split partials (16 MB shared)
__device__ int   g_idx[2][NTOK];
__device__ float g_gate[2][NTOK];
__device__ int   g_list[2][NTOK];
__device__ int   g_ntile[2];
__device__ int2  g_tiles[2][MAXTILE];         // x = e | (cnt<<16), y = base in g_list

// ---------------- packed f32x2 FMA (Blackwell) ------------------------------
__device__ __forceinline__ float2 ffma2(float2 a, float2 b, float2 c) {
    float2 d;
    asm("fma.rn.f32x2 %0, %1, %2, %3;"
        : "=l"(*reinterpret_cast<unsigned long long*>(&d))
        : "l"(*reinterpret_cast<const unsigned long long*>(&a)),
          "l"(*reinterpret_cast<const unsigned long long*>(&b)),
          "l"(*reinterpret_cast<const unsigned long long*>(&c)));
    return d;
}

__device__ __forceinline__ float2 ldcs2(const float* p) {
    float2 v;
    asm("ld.global.cs.v2.f32 {%0, %1}, [%2];"
        : "=f"(v.x), "=f"(v.y) : "l"(p));
    return v;
}

__device__ __forceinline__ float gelu_f(float v) {
    return 0.5f * v * (1.0f + erff(v * 0.70710678118654752440f));
}

// ---------------- layer-1 gating ----------------------------------------------
// grid = NTOK/8 blocks, 64 threads (one expert per thread), 8 tokens per block.
template<int DIN>
__global__ void gate_kernel(const float* __restrict__ X,
                            const float* __restrict__ EMB,
                            float scale, int layer) {
    const int e = threadIdx.x;          // 0..63
    const int t0 = blockIdx.x * 8;
    const float* er = EMB + (size_t)e * DIN;

    float2 acc[8];
    #pragma unroll
    for (int t = 0; t < 8; t++) acc[t] = make_float2(0.f, 0.f);

    #pragma unroll 2
    for (int k4 = 0; k4 < DIN / 4; k4++) {
        float4 w = *(const float4*)(er + k4 * 4);
        float2 w01 = make_float2(w.x, w.y);
        float2 w23 = make_float2(w.z, w.w);
        #pragma unroll
        for (int t = 0; t < 8; t++) {
            float4 xv = *(const float4*)(X + (size_t)(t0 + t) * DIN + k4 * 4);
            acc[t] = ffma2(make_float2(xv.x, xv.y), w01, acc[t]);
            acc[t] = ffma2(make_float2(xv.z, xv.w), w23, acc[t]);
        }
    }

    __shared__ float s_logit[8][NEXP];
    #pragma unroll
    for (int t = 0; t < 8; t++) s_logit[t][e] = (acc[t].x + acc[t].y) * scale;
    __syncthreads();

    if (threadIdx.x < 8) {
        const int t = threadIdx.x;
        float m = s_logit[t][0]; int mi = 0;
        for (int i = 1; i < NEXP; i++)
            if (s_logit[t][i] > m) { m = s_logit[t][i]; mi = i; }
        float s = 0.f;
        for (int i = 0; i < NEXP; i++) s += expf(s_logit[t][i] - m);
        g_idx[layer][t0 + t]  = mi;
        g_gate[layer][t0 + t] = 1.0f / s;   // max softmax prob
    }
}

// ---------------- group: histogram + prefix + scatter + tile list ------------
__global__ void group_kernel(int layer) {
    __shared__ int s_cnt[NEXP], s_cur[NEXP];
    const int t = threadIdx.x;
    if (t < NEXP) s_cnt[t] = 0;
    __syncthreads();
    for (int i = t; i < NTOK; i += blockDim.x)
        atomicAdd(&s_cnt[g_idx[layer][i]], 1);
    __syncthreads();
    if (t == 0) {
        int a = 0, nt = 0;
        for (int e = 0; e < NEXP; e++) {
            s_cur[e] = a;
            const int c = s_cnt[e];
            for (int t0 = 0; t0 < c; t0 += 16) {
                int cnt = (c - t0 < 16) ? (c - t0) : 16;
                g_tiles[layer][nt++] = make_int2(e | (cnt << 16), a + t0);
            }
            a += c;
        }
        g_ntile[layer] = nt;
    }
    __syncthreads();
    for (int i = t; i < NTOK; i += blockDim.x) {
        int e = g_idx[layer][i];
        int p = atomicAdd(&s_cur[e], 1);
        g_list[layer][p] = i;
    }
}

// ---------------- FMA micro-block: 8 k-rows x 16 tokens ----------------------
// NOTE: s_x type carries the true row stride (KLEN) — checked at compile time.
template<int KLEN>
__device__ __forceinline__ void fma_block(float2 (&acc)[16],
                                          const float (&s_x)[16][KLEN],
                                          int kb, const float2 (&wb)[8]) {
    #pragma unroll
    for (int j = 0; j < 16; j++) {
        float4 xa = *(const float4*)&s_x[j][kb];      // broadcast LDS.128
        float4 xb = *(const float4*)&s_x[j][kb + 4];
        acc[j] = ffma2(make_float2(xa.x, xa.x), wb[0], acc[j]);
        acc[j] = ffma2(make_float2(xa.y, xa.y), wb[1], acc[j]);
        acc[j] = ffma2(make_float2(xa.z, xa.z), wb[2], acc[j]);
        acc[j] = ffma2(make_float2(xa.w, xa.w), wb[3], acc[j]);
        acc[j] = ffma2(make_float2(xb.x, xb.x), wb[4], acc[j]);
        acc[j] = ffma2(make_float2(xb.y, xb.y), wb[5], acc[j]);
        acc[j] = ffma2(make_float2(xb.z, xb.z), wb[6], acc[j]);
        acc[j] = ffma2(make_float2(xb.w, xb.w), wb[7], acc[j]);
    }
}

// ---------------- grouped expert FC: one 16-token tile per CTA ---------------
// grid = (DOUT/256, 128, DIN/KLEN); 128 threads.
// Warp wg owns cols [blk*256 + wg*64, +64); lane owns 2 cols (LDG.64 W rows).
// Double-buffered 8-row W batches (no copies). Raw partial sums out.
template<int DIN, int DOUT, int KLEN>
__global__ void __launch_bounds__(128, 5)
fc_kernel(const float* __restrict__ X,
          const float* __restrict__ W,
          int layer,
          float* __restrict__ OUT) {
    const int slot = blockIdx.y;
    if (slot >= g_ntile[layer]) return;
    const int2 tile = g_tiles[layer][slot];
    const int e = tile.x & 0xFFFF;
    const int cnt = tile.x >> 16;
    const int tbase = tile.y;

    const int lane = threadIdx.x & 31;
    const int wg = threadIdx.x >> 5;
    const int colBase = blockIdx.x * 256 + wg * 64 + lane * 2;
    const int k0 = blockIdx.z * KLEN;

    __shared__ float s_x[16][KLEN];
    __shared__ int s_row[16];

    const float* Wb = W + (size_t)e * DIN * DOUT + (size_t)k0 * DOUT + colBase;

    // preload both W batches early (hide under X staging)
    float2 wb0[8], wb1[8];
    #pragma unroll
    for (int u = 0; u < 8; u++) wb0[u] = ldcs2(Wb + (size_t)u * DOUT);
    #pragma unroll
    for (int u = 0; u < 8; u++) wb1[u] = ldcs2(Wb + (size_t)(8 + u) * DOUT);

    if (threadIdx.x < 16)
        s_row[threadIdx.x] = (threadIdx.x < cnt)
                             ? g_list[layer][tbase + threadIdx.x] : -1;
    __syncthreads();

    // stage 16 x KLEN chunk of X (float4, coalesced)
    constexpr int K4 = KLEN / 4;
    #pragma unroll
    for (int i = threadIdx.x; i < 16 * K4; i += 128) {
        int t = i / K4, k4 = i % K4;
        int r = s_row[t];
        float4 v = (r >= 0)
            ? *(const float4*)(X + (size_t)r * DIN + k0 + k4 * 4)
            : make_float4(0.f, 0.f, 0.f, 0.f);
        *(float4*)&s_x[t][k4 * 4] = v;
    }
    __syncthreads();

    float2 acc[16];
    #pragma unroll
    for (int j = 0; j < 16; j++) acc[j] = make_float2(0.f, 0.f);

    #pragma unroll 1
    for (int kb = 0; kb < KLEN; kb += 16) {
        fma_block<KLEN>(acc, s_x, kb, wb0);
        if (kb + 16 < KLEN) {
            const float* wn = Wb + (size_t)(kb + 16) * DOUT;
            #pragma unroll
            for (int u = 0; u < 8; u++) wb0[u] = ldcs2(wn + (size_t)u * DOUT);
        }
        fma_block<KLEN>(acc, s_x, kb + 8, wb1);
        if (kb + 24 < KLEN) {
            const float* wn = Wb + (size_t)(kb + 24) * DOUT;
            #pragma unroll
            for (int u = 0; u < 8; u++) wb1[u] = ldcs2(wn + (size_t)u * DOUT);
        }
    }

    // write raw partial sums (per-split slab)
    #pragma unroll
    for (int j = 0; j < 16; j++) {
        int r = s_row[j];
        if (r < 0) continue;
        *(float2*)(OUT + ((size_t)blockIdx.z * NTOK + r) * DOUT + colBase) = acc[j];
    }
}

// ---------------- fused epi1 + layer-2 gating ---------------------------------
// grid = NTOK/4 blocks, 128 threads. Phase 1: h = gelu((part0+part1+b1)*gate)
// for 4 tokens into smem (33 KB) + write g_h. Phase 2: layer-2 logits from smem.
__global__ void mid_kernel(const float* __restrict__ B1v,
                           const float* __restrict__ EMB2,
                           float scale,
                           float* __restrict__ H) {
    __shared__ float s_h[4][HIDV];
    __shared__ float s_logit[4][NEXP];
    const int t0 = blockIdx.x * 4;

    // phase 1: reconstruct 4 h rows
    for (int i = threadIdx.x; i < 4 * (HIDV / 4); i += 128) {
        const int t = i / (HIDV / 4), c = (i % (HIDV / 4)) * 4;
        const int tok = t0 + t;
        const int e = g_idx[0][tok];
        const float g = g_gate[0][tok];
        float4 s = *(const float4*)(B1v + (size_t)e * HIDV + c);
        #pragma unroll
        for (int z = 0; z < 2; z++) {
            float4 p = *(const float4*)&g_part[((size_t)z * NTOK + tok) * HIDV + c];
            s.x += p.x; s.y += p.y; s.z += p.z; s.w += p.w;
        }
        float4 hv = make_float4(gelu_f(s.x * g), gelu_f(s.y * g),
                                gelu_f(s.z * g), gelu_f(s.w * g));
        *(float4*)&s_h[t][c] = hv;
        *(float4*)(H + (size_t)tok * HIDV + c) = hv;
    }
    __syncthreads();

    // phase 2: gating. thread = (e = tid&63, half = tid>>6 -> 2 tokens)
    const int e = threadIdx.x & 63;
    const int tj = (threadIdx.x >> 6) * 2;
    const float* er = EMB2 + (size_t)e * HIDV;

    float2 acc[2];
    acc[0] = make_float2(0.f, 0.f);
    acc[1] = make_float2(0.f, 0.f);

    #pragma unroll 2
    for (int k4 = 0; k4 < HIDV / 4; k4++) {
        float4 w = *(const float4*)(er + k4 * 4);
        float2 w01 = make_float2(w.x, w.y);
        float2 w23 = make_float2(w.z, w.w);
        #pragma unroll
        for (int t = 0; t < 2; t++) {
            float4 xv = *(const float4*)&s_h[tj + t][k4 * 4];
            acc[t] = ffma2(make_float2(xv.x, xv.y), w01, acc[t]);
            acc[t] = ffma2(make_float2(xv.z, xv.w), w23, acc[t]);
        }
    }
    #pragma unroll
    for (int t = 0; t < 2; t++)
        s_logit[tj + t][e] = (acc[t].x + acc[t].y) * scale;
    __syncthreads();

    if (threadIdx.x < 4) {
        const int t = threadIdx.x;
        float m = s_logit[t][0]; int mi = 0;
        for (int i = 1; i < NEXP; i++)
            if (s_logit[t][i] > m) { m = s_logit[t][i]; mi = i; }
        float s = 0.f;
        for (int i = 0; i < NEXP; i++) s += expf(s_logit[t][i] - m);
        g_idx[1][t0 + t]  = mi;
        g_gate[1][t0 + t] = 1.0f / s;
    }
}

// ---------------- FC2 combine: bias + gate -> out ----------------------------
__global__ void epi2_kernel(const float* __restrict__ B2v,
                            float* __restrict__ OUT) {
    const int t = blockIdx.x;
    const int c = threadIdx.x * 4;
    const int e = g_idx[1][t];
    const float g = g_gate[1][t];
    float4 s = *(const float4*)(B2v + (size_t)e * DIMV + c);
    #pragma unroll
    for (int z = 0; z < 8; z++) {
        float4 p = *(const float4*)&g_part[((size_t)z * NTOK + t) * DIMV + c];
        s.x += p.x; s.y += p.y; s.z += p.z; s.w += p.w;
    }
    *(float4*)(OUT + (size_t)t * DIMV + c) =
        make_float4(s.x * g, s.y * g, s.z * g, s.w * g);
}

// ---------------- launch ------------------------------------------------------
extern "C" void kernel_launch(void* const* d_in, const int* in_sizes, int n_in,
                              void* d_out, int out_size) {
    const float* x    = (const float*)d_in[0];
    const float* emb1 = (const float*)d_in[1];
    const float* W1   = (const float*)d_in[2];
    const float* b1   = (const float*)d_in[3];
    const float* emb2 = (const float*)d_in[4];
    const float* W2   = (const float*)d_in[5];
    const float* b2   = (const float*)d_in[6];
    float* out = (float*)d_out;

    void* hp = nullptr;
    cudaGetSymbolAddress(&hp, g_h);
    float* h = (float*)hp;
    void* pp = nullptr;
    cudaGetSymbolAddress(&pp, g_part);
    float* part = (float*)pp;

    const float scale1 = 0.044194173824159216f;   // 1/sqrt(512)
    const float scale2 = 0.022097086912079612f;   // 1/sqrt(2048)

    gate_kernel<DIMV><<<NTOK / 8, 64>>>(x, emb1, scale1, 0);
    group_kernel<<<1, 256>>>(0);
    // FC1: K=512 split x2 (KLEN=256), one tile per CTA, 128 tile slots
    fc_kernel<DIMV, HIDV, 256>
        <<<dim3(HIDV / 256, 128, 2), 128>>>(x, W1, 0, part);
    // fused epi1 + gate2 (4 tokens per block, 33 KB smem)
    mid_kernel<<<NTOK / 4, 128>>>(b1, emb2, scale2, h);
    group_kernel<<<1, 256>>>(1);
    // FC2: K=2048 split x8 (KLEN=256), one tile per CTA
    fc_kernel<HIDV, DIMV, 256>
        <<<dim3(DIMV / 256, 128, 8), 128>>>(h, W2, 1, part);
    epi2_kernel<<<NTOK, 128>>>(b2, out);
}

// round 12
// speedup vs baseline: 2.9236x; 1.3082x over previous
#include <cuda_runtime.h>
#include <math.h>

#define NTOK 1024
#define DIMV 512
#define HIDV 2048
#define NEXP 64
#define MAXTILE 160

// ---------------- scratch (device globals; no allocation allowed) ----------
__device__ float g_h[NTOK * HIDV];            // hidden after GELU (8 MB)
__device__ float g_part[2 * NTOK * HIDV];     // K-split partials (16 MB shared)
__device__ float g_glog[8 * NTOK * NEXP];     // gating logit partials (2 MB)
__device__ int   g_idx[2][NTOK];
__device__ float g_gate[2][NTOK];
__device__ int   g_list[2][NTOK];
__device__ int   g_ntile[2];
__device__ int2  g_tiles[2][MAXTILE];         // x = e | (cnt<<16), y = base in g_list

// ---------------- packed f32x2 FMA (Blackwell) ------------------------------
__device__ __forceinline__ float2 ffma2(float2 a, float2 b, float2 c) {
    float2 d;
    asm("fma.rn.f32x2 %0, %1, %2, %3;"
        : "=l"(*reinterpret_cast<unsigned long long*>(&d))
        : "l"(*reinterpret_cast<const unsigned long long*>(&a)),
          "l"(*reinterpret_cast<const unsigned long long*>(&b)),
          "l"(*reinterpret_cast<const unsigned long long*>(&c)));
    return d;
}

__device__ __forceinline__ float2 ldcs2(const float* p) {
    float2 v;
    asm("ld.global.cs.v2.f32 {%0, %1}, [%2];"
        : "=f"(v.x), "=f"(v.y) : "l"(p));
    return v;
}

__device__ __forceinline__ float gelu_f(float v) {
    return 0.5f * v * (1.0f + erff(v * 0.70710678118654752440f));
}

// ---------------- gating logits: tiled GEMM [32 tok x 64 exp] per CTA --------
// grid = (NTOK/32, DIN/KLEN); 128 threads.
// Thread (tq = tid>>4, eq = tid&15) owns tokens tq*4..+3 and experts
// {eq, eq+16, eq+32, eq+48} (strided -> conflict-free smem reads).
template<int DIN, int KLEN>
__global__ void glogit_kernel(const float* __restrict__ X,
                              const float* __restrict__ EMB,
                              float* __restrict__ GLOG) {
    const int t0 = blockIdx.x * 32;
    const int k0 = blockIdx.y * KLEN;
    const int eq = threadIdx.x & 15;
    const int tq = threadIdx.x >> 4;     // 0..7

    __shared__ float s_xT[64][36];       // [kk][token], stride mult-of-4 for LDS.128
    __shared__ float s_e[64][66];        // [expert][kk], stride mult-of-2 for LDS.64

    // acc[j][p]: token tq*4+j, expert pair p: p0 = (eq, eq+16), p1 = (eq+32, eq+48)
    float2 acc[4][2];
    #pragma unroll
    for (int j = 0; j < 4; j++) {
        acc[j][0] = make_float2(0.f, 0.f);
        acc[j][1] = make_float2(0.f, 0.f);
    }

    for (int kc = 0; kc < KLEN; kc += 64) {
        __syncthreads();
        // stage x transposed: 32 tokens x 64 k
        #pragma unroll
        for (int i = threadIdx.x; i < 512; i += 128) {
            int t = i >> 4, k4 = i & 15;
            float4 v = *(const float4*)(X + (size_t)(t0 + t) * DIN + k0 + kc + k4 * 4);
            s_xT[k4 * 4 + 0][t] = v.x;
            s_xT[k4 * 4 + 1][t] = v.y;
            s_xT[k4 * 4 + 2][t] = v.z;
            s_xT[k4 * 4 + 3][t] = v.w;
        }
        // stage emb rows: 64 experts x 64 k
        #pragma unroll
        for (int i = threadIdx.x; i < 1024; i += 128) {
            int e = i >> 4, k4 = i & 15;
            float4 v = *(const float4*)(EMB + (size_t)e * DIN + k0 + kc + k4 * 4);
            s_e[e][k4 * 4 + 0] = v.x;
            s_e[e][k4 * 4 + 1] = v.y;
            s_e[e][k4 * 4 + 2] = v.z;
            s_e[e][k4 * 4 + 3] = v.w;
        }
        __syncthreads();

        #pragma unroll 8
        for (int kk = 0; kk < 64; kk += 2) {
            float2 e0 = *(const float2*)&s_e[eq][kk];        // exp eq   @ kk,kk+1
            float2 e1 = *(const float2*)&s_e[eq + 16][kk];
            float2 e2 = *(const float2*)&s_e[eq + 32][kk];
            float2 e3 = *(const float2*)&s_e[eq + 48][kk];
            float4 x0 = *(const float4*)&s_xT[kk][tq * 4];   // 4 tokens @ kk
            float4 x1 = *(const float4*)&s_xT[kk + 1][tq * 4];

            float2 p0a = make_float2(e0.x, e1.x);   // kk:   (eq, eq+16)
            float2 p1a = make_float2(e2.x, e3.x);   // kk:   (eq+32, eq+48)
            float2 p0b = make_float2(e0.y, e1.y);   // kk+1
            float2 p1b = make_float2(e2.y, e3.y);

            acc[0][0] = ffma2(make_float2(x0.x, x0.x), p0a, acc[0][0]);
            acc[0][1] = ffma2(make_float2(x0.x, x0.x), p1a, acc[0][1]);
            acc[1][0] = ffma2(make_float2(x0.y, x0.y), p0a, acc[1][0]);
            acc[1][1] = ffma2(make_float2(x0.y, x0.y), p1a, acc[1][1]);
            acc[2][0] = ffma2(make_float2(x0.z, x0.z), p0a, acc[2][0]);
            acc[2][1] = ffma2(make_float2(x0.z, x0.z), p1a, acc[2][1]);
            acc[3][0] = ffma2(make_float2(x0.w, x0.w), p0a, acc[3][0]);
            acc[3][1] = ffma2(make_float2(x0.w, x0.w), p1a, acc[3][1]);

            acc[0][0] = ffma2(make_float2(x1.x, x1.x), p0b, acc[0][0]);
            acc[0][1] = ffma2(make_float2(x1.x, x1.x), p1b, acc[0][1]);
            acc[1][0] = ffma2(make_float2(x1.y, x1.y), p0b, acc[1][0]);
            acc[1][1] = ffma2(make_float2(x1.y, x1.y), p1b, acc[1][1]);
            acc[2][0] = ffma2(make_float2(x1.z, x1.z), p0b, acc[2][0]);
            acc[2][1] = ffma2(make_float2(x1.z, x1.z), p1b, acc[2][1]);
            acc[3][0] = ffma2(make_float2(x1.w, x1.w), p0b, acc[3][0]);
            acc[3][1] = ffma2(make_float2(x1.w, x1.w), p1b, acc[3][1]);
        }
    }

    // write logit partials
    #pragma unroll
    for (int j = 0; j < 4; j++) {
        float* gp = GLOG + ((size_t)blockIdx.y * NTOK + t0 + tq * 4 + j) * NEXP;
        gp[eq]      = acc[j][0].x;
        gp[eq + 16] = acc[j][0].y;
        gp[eq + 32] = acc[j][1].x;
        gp[eq + 48] = acc[j][1].y;
    }
}

// ---------------- gating finalize: softmax max-prob + argmax -----------------
// grid = NTOK blocks, 32 threads; lane owns experts {lane, lane+32}.
template<int NSPLIT>
__global__ void gfinal_kernel(const float* __restrict__ GLOG,
                              float scale, int layer) {
    const int t = blockIdx.x;
    const int l = threadIdx.x;
    float v0 = 0.f, v1 = 0.f;
    #pragma unroll
    for (int z = 0; z < NSPLIT; z++) {
        const float* gp = GLOG + ((size_t)z * NTOK + t) * NEXP;
        v0 += gp[l];
        v1 += gp[l + 32];
    }
    v0 *= scale; v1 *= scale;

    float m; int mi;
    if (v0 >= v1) { m = v0; mi = l; } else { m = v1; mi = l + 32; }
    #pragma unroll
    for (int off = 16; off; off >>= 1) {
        float om = __shfl_xor_sync(0xFFFFFFFFu, m, off);
        int omi = __shfl_xor_sync(0xFFFFFFFFu, mi, off);
        if (om > m || (om == m && omi < mi)) { m = om; mi = omi; }
    }
    float s = expf(v0 - m) + expf(v1 - m);
    #pragma unroll
    for (int off = 16; off; off >>= 1)
        s += __shfl_xor_sync(0xFFFFFFFFu, s, off);

    if (l == 0) {
        g_idx[layer][t]  = mi;
        g_gate[layer][t] = 1.0f / s;   // max softmax prob
    }
}

// ---------------- group: histogram + prefix + scatter + tile list ------------
__global__ void group_kernel(int layer) {
    __shared__ int s_cnt[NEXP], s_cur[NEXP];
    const int t = threadIdx.x;
    if (t < NEXP) s_cnt[t] = 0;
    __syncthreads();
    for (int i = t; i < NTOK; i += blockDim.x)
        atomicAdd(&s_cnt[g_idx[layer][i]], 1);
    __syncthreads();
    if (t == 0) {
        int a = 0, nt = 0;
        for (int e = 0; e < NEXP; e++) {
            s_cur[e] = a;
            const int c = s_cnt[e];
            for (int t0 = 0; t0 < c; t0 += 16) {
                int cnt = (c - t0 < 16) ? (c - t0) : 16;
                g_tiles[layer][nt++] = make_int2(e | (cnt << 16), a + t0);
            }
            a += c;
        }
        g_ntile[layer] = nt;
    }
    __syncthreads();
    for (int i = t; i < NTOK; i += blockDim.x) {
        int e = g_idx[layer][i];
        int p = atomicAdd(&s_cur[e], 1);
        g_list[layer][p] = i;
    }
}

// ---------------- FMA micro-block: 8 k-rows x 16 tokens ----------------------
template<int KLEN>
__device__ __forceinline__ void fma_block(float2 (&acc)[16],
                                          const float (&s_x)[16][KLEN],
                                          int kb, const float2 (&wb)[8]) {
    #pragma unroll
    for (int j = 0; j < 16; j++) {
        float4 xa = *(const float4*)&s_x[j][kb];      // broadcast LDS.128
        float4 xb = *(const float4*)&s_x[j][kb + 4];
        acc[j] = ffma2(make_float2(xa.x, xa.x), wb[0], acc[j]);
        acc[j] = ffma2(make_float2(xa.y, xa.y), wb[1], acc[j]);
        acc[j] = ffma2(make_float2(xa.z, xa.z), wb[2], acc[j]);
        acc[j] = ffma2(make_float2(xa.w, xa.w), wb[3], acc[j]);
        acc[j] = ffma2(make_float2(xb.x, xb.x), wb[4], acc[j]);
        acc[j] = ffma2(make_float2(xb.y, xb.y), wb[5], acc[j]);
        acc[j] = ffma2(make_float2(xb.z, xb.z), wb[6], acc[j]);
        acc[j] = ffma2(make_float2(xb.w, xb.w), wb[7], acc[j]);
    }
}

// ---------------- grouped expert FC: one 16-token tile per CTA ---------------
template<int DIN, int DOUT, int KLEN>
__global__ void __launch_bounds__(128, 5)
fc_kernel(const float* __restrict__ X,
          const float* __restrict__ W,
          int layer,
          float* __restrict__ OUT) {
    const int slot = blockIdx.y;
    if (slot >= g_ntile[layer]) return;
    const int2 tile = g_tiles[layer][slot];
    const int e = tile.x & 0xFFFF;
    const int cnt = tile.x >> 16;
    const int tbase = tile.y;

    const int lane = threadIdx.x & 31;
    const int wg = threadIdx.x >> 5;
    const int colBase = blockIdx.x * 256 + wg * 64 + lane * 2;
    const int k0 = blockIdx.z * KLEN;

    __shared__ float s_x[16][KLEN];
    __shared__ int s_row[16];

    const float* Wb = W + (size_t)e * DIN * DOUT + (size_t)k0 * DOUT + colBase;

    // preload both W batches early (hide under X staging)
    float2 wb0[8], wb1[8];
    #pragma unroll
    for (int u = 0; u < 8; u++) wb0[u] = ldcs2(Wb + (size_t)u * DOUT);
    #pragma unroll
    for (int u = 0; u < 8; u++) wb1[u] = ldcs2(Wb + (size_t)(8 + u) * DOUT);

    if (threadIdx.x < 16)
        s_row[threadIdx.x] = (threadIdx.x < cnt)
                             ? g_list[layer][tbase + threadIdx.x] : -1;
    __syncthreads();

    // stage 16 x KLEN chunk of X (float4, coalesced)
    constexpr int K4 = KLEN / 4;
    #pragma unroll
    for (int i = threadIdx.x; i < 16 * K4; i += 128) {
        int t = i / K4, k4 = i % K4;
        int r = s_row[t];
        float4 v = (r >= 0)
            ? *(const float4*)(X + (size_t)r * DIN + k0 + k4 * 4)
            : make_float4(0.f, 0.f, 0.f, 0.f);
        *(float4*)&s_x[t][k4 * 4] = v;
    }
    __syncthreads();

    float2 acc[16];
    #pragma unroll
    for (int j = 0; j < 16; j++) acc[j] = make_float2(0.f, 0.f);

    #pragma unroll 1
    for (int kb = 0; kb < KLEN; kb += 16) {
        fma_block<KLEN>(acc, s_x, kb, wb0);
        if (kb + 16 < KLEN) {
            const float* wn = Wb + (size_t)(kb + 16) * DOUT;
            #pragma unroll
            for (int u = 0; u < 8; u++) wb0[u] = ldcs2(wn + (size_t)u * DOUT);
        }
        fma_block<KLEN>(acc, s_x, kb + 8, wb1);
        if (kb + 24 < KLEN) {
            const float* wn = Wb + (size_t)(kb + 24) * DOUT;
            #pragma unroll
            for (int u = 0; u < 8; u++) wb1[u] = ldcs2(wn + (size_t)u * DOUT);
        }
    }

    // write raw partial sums (per-split slab)
    #pragma unroll
    for (int j = 0; j < 16; j++) {
        int r = s_row[j];
        if (r < 0) continue;
        *(float2*)(OUT + ((size_t)blockIdx.z * NTOK + r) * DOUT + colBase) = acc[j];
    }
}

// ---------------- FC1 combine: bias + gate + gelu -> h -----------------------
__global__ void epi1_kernel(const float* __restrict__ B1v,
                            float* __restrict__ H) {
    const int t = blockIdx.x;
    const int c = threadIdx.x * 4;
    const int e = g_idx[0][t];
    const float g = g_gate[0][t];
    float4 s = *(const float4*)(B1v + (size_t)e * HIDV + c);
    #pragma unroll
    for (int z = 0; z < 2; z++) {
        float4 p = *(const float4*)&g_part[((size_t)z * NTOK + t) * HIDV + c];
        s.x += p.x; s.y += p.y; s.z += p.z; s.w += p.w;
    }
    *(float4*)(H + (size_t)t * HIDV + c) =
        make_float4(gelu_f(s.x * g), gelu_f(s.y * g),
                    gelu_f(s.z * g), gelu_f(s.w * g));
}

// ---------------- FC2 combine: bias + gate -> out ----------------------------
__global__ void epi2_kernel(const float* __restrict__ B2v,
                            float* __restrict__ OUT) {
    const int t = blockIdx.x;
    const int c = threadIdx.x * 4;
    const int e = g_idx[1][t];
    const float g = g_gate[1][t];
    float4 s = *(const float4*)(B2v + (size_t)e * DIMV + c);
    #pragma unroll
    for (int z = 0; z < 8; z++) {
        float4 p = *(const float4*)&g_part[((size_t)z * NTOK + t) * DIMV + c];
        s.x += p.x; s.y += p.y; s.z += p.z; s.w += p.w;
    }
    *(float4*)(OUT + (size_t)t * DIMV + c) =
        make_float4(s.x * g, s.y * g, s.z * g, s.w * g);
}

// ---------------- launch ------------------------------------------------------
extern "C" void kernel_launch(void* const* d_in, const int* in_sizes, int n_in,
                              void* d_out, int out_size) {
    const float* x    = (const float*)d_in[0];
    const float* emb1 = (const float*)d_in[1];
    const float* W1   = (const float*)d_in[2];
    const float* b1   = (const float*)d_in[3];
    const float* emb2 = (const float*)d_in[4];
    const float* W2   = (const float*)d_in[5];
    const float* b2   = (const float*)d_in[6];
    float* out = (float*)d_out;

    void* hp = nullptr;
    cudaGetSymbolAddress(&hp, g_h);
    float* h = (float*)hp;
    void* pp = nullptr;
    cudaGetSymbolAddress(&pp, g_part);
    float* part = (float*)pp;
    void* gp = nullptr;
    cudaGetSymbolAddress(&gp, g_glog);
    float* glog = (float*)gp;

    const float scale1 = 0.044194173824159216f;   // 1/sqrt(512)
    const float scale2 = 0.022097086912079612f;   // 1/sqrt(2048)

    // layer-1 gating: tiled logit GEMM (K split x2) + finalize
    glogit_kernel<DIMV, 256><<<dim3(NTOK / 32, 2), 128>>>(x, emb1, glog);
    gfinal_kernel<2><<<NTOK, 32>>>(glog, scale1, 0);
    group_kernel<<<1, 256>>>(0);
    // FC1: K=512 split x2 (KLEN=256), one tile per CTA, 128 tile slots
    fc_kernel<DIMV, HIDV, 256>
        <<<dim3(HIDV / 256, 128, 2), 128>>>(x, W1, 0, part);
    epi1_kernel<<<NTOK, 512>>>(b1, h);

    // layer-2 gating (K split x8)
    glogit_kernel<HIDV, 256><<<dim3(NTOK / 32, 8), 128>>>(h, emb2, glog);
    gfinal_kernel<8><<<NTOK, 32>>>(glog, scale2, 1);
    group_kernel<<<1, 256>>>(1);
    // FC2: K=2048 split x8 (KLEN=256), one tile per CTA
    fc_kernel<HIDV, DIMV, 256>
        <<<dim3(DIMV / 256, 128, 8), 128>>>(h, W2, 1, part);
    epi2_kernel<<<NTOK, 128>>>(b2, out);
}

// round 16
// speedup vs baseline: 3.1190x; 1.0668x over previous
#include <cuda_runtime.h>
#include <math.h>

#define NTOK 1024
#define DIMV 512
#define HIDV 2048
#define NEXP 64
#define MAXTILE 160

// ---------------- scratch (device globals; no allocation allowed) ----------
__device__ float g_h[NTOK * HIDV];            // hidden after GELU (8 MB)
__device__ float g_part[2 * NTOK * HIDV];     // K-split partials (16 MB shared)
__device__ float g_glog[8 * NTOK * NEXP];     // gating logit partials (2 MB)
__device__ int   g_idx[2][NTOK];
__device__ float g_gate[2][NTOK];
__device__ int   g_list[2][NTOK];
__device__ int   g_ntile[2];
__device__ int2  g_tiles[2][MAXTILE];         // x = e | (cnt<<16), y = base in g_list

// ---------------- packed f32x2 FMA (Blackwell) ------------------------------
__device__ __forceinline__ float2 ffma2(float2 a, float2 b, float2 c) {
    float2 d;
    asm("fma.rn.f32x2 %0, %1, %2, %3;"
        : "=l"(*reinterpret_cast<unsigned long long*>(&d))
        : "l"(*reinterpret_cast<const unsigned long long*>(&a)),
          "l"(*reinterpret_cast<const unsigned long long*>(&b)),
          "l"(*reinterpret_cast<const unsigned long long*>(&c)));
    return d;
}

__device__ __forceinline__ float4 ldcs4(const float* p) {
    float4 v;
    asm("ld.global.cs.v4.f32 {%0, %1, %2, %3}, [%4];"
        : "=f"(v.x), "=f"(v.y), "=f"(v.z), "=f"(v.w) : "l"(p));
    return v;
}

__device__ __forceinline__ float gelu_f(float v) {
    return 0.5f * v * (1.0f + erff(v * 0.70710678118654752440f));
}

// ---------------- gating logits: tiled GEMM [32 tok x 64 exp] per CTA --------
template<int DIN, int KLEN>
__global__ void glogit_kernel(const float* __restrict__ X,
                              const float* __restrict__ EMB,
                              float* __restrict__ GLOG) {
    const int t0 = blockIdx.x * 32;
    const int k0 = blockIdx.y * KLEN;
    const int eq = threadIdx.x & 15;
    const int tq = threadIdx.x >> 4;     // 0..7

    __shared__ float s_xT[64][36];       // [kk][token]
    __shared__ float s_e[64][66];        // [expert][kk]

    float2 acc[4][2];
    #pragma unroll
    for (int j = 0; j < 4; j++) {
        acc[j][0] = make_float2(0.f, 0.f);
        acc[j][1] = make_float2(0.f, 0.f);
    }

    for (int kc = 0; kc < KLEN; kc += 64) {
        __syncthreads();
        #pragma unroll
        for (int i = threadIdx.x; i < 512; i += 128) {
            int t = i >> 4, k4 = i & 15;
            float4 v = *(const float4*)(X + (size_t)(t0 + t) * DIN + k0 + kc + k4 * 4);
            s_xT[k4 * 4 + 0][t] = v.x;
            s_xT[k4 * 4 + 1][t] = v.y;
            s_xT[k4 * 4 + 2][t] = v.z;
            s_xT[k4 * 4 + 3][t] = v.w;
        }
        #pragma unroll
        for (int i = threadIdx.x; i < 1024; i += 128) {
            int e = i >> 4, k4 = i & 15;
            float4 v = *(const float4*)(EMB + (size_t)e * DIN + k0 + kc + k4 * 4);
            s_e[e][k4 * 4 + 0] = v.x;
            s_e[e][k4 * 4 + 1] = v.y;
            s_e[e][k4 * 4 + 2] = v.z;
            s_e[e][k4 * 4 + 3] = v.w;
        }
        __syncthreads();

        #pragma unroll 8
        for (int kk = 0; kk < 64; kk += 2) {
            float2 e0 = *(const float2*)&s_e[eq][kk];
            float2 e1 = *(const float2*)&s_e[eq + 16][kk];
            float2 e2 = *(const float2*)&s_e[eq + 32][kk];
            float2 e3 = *(const float2*)&s_e[eq + 48][kk];
            float4 x0 = *(const float4*)&s_xT[kk][tq * 4];
            float4 x1 = *(const float4*)&s_xT[kk + 1][tq * 4];

            float2 p0a = make_float2(e0.x, e1.x);
            float2 p1a = make_float2(e2.x, e3.x);
            float2 p0b = make_float2(e0.y, e1.y);
            float2 p1b = make_float2(e2.y, e3.y);

            acc[0][0] = ffma2(make_float2(x0.x, x0.x), p0a, acc[0][0]);
            acc[0][1] = ffma2(make_float2(x0.x, x0.x), p1a, acc[0][1]);
            acc[1][0] = ffma2(make_float2(x0.y, x0.y), p0a, acc[1][0]);
            acc[1][1] = ffma2(make_float2(x0.y, x0.y), p1a, acc[1][1]);
            acc[2][0] = ffma2(make_float2(x0.z, x0.z), p0a, acc[2][0]);
            acc[2][1] = ffma2(make_float2(x0.z, x0.z), p1a, acc[2][1]);
            acc[3][0] = ffma2(make_float2(x0.w, x0.w), p0a, acc[3][0]);
            acc[3][1] = ffma2(make_float2(x0.w, x0.w), p1a, acc[3][1]);

            acc[0][0] = ffma2(make_float2(x1.x, x1.x), p0b, acc[0][0]);
            acc[0][1] = ffma2(make_float2(x1.x, x1.x), p1b, acc[0][1]);
            acc[1][0] = ffma2(make_float2(x1.y, x1.y), p0b, acc[1][0]);
            acc[1][1] = ffma2(make_float2(x1.y, x1.y), p1b, acc[1][1]);
            acc[2][0] = ffma2(make_float2(x1.z, x1.z), p0b, acc[2][0]);
            acc[2][1] = ffma2(make_float2(x1.z, x1.z), p1b, acc[2][1]);
            acc[3][0] = ffma2(make_float2(x1.w, x1.w), p0b, acc[3][0]);
            acc[3][1] = ffma2(make_float2(x1.w, x1.w), p1b, acc[3][1]);
        }
    }

    #pragma unroll
    for (int j = 0; j < 4; j++) {
        float* gp = GLOG + ((size_t)blockIdx.y * NTOK + t0 + tq * 4 + j) * NEXP;
        gp[eq]      = acc[j][0].x;
        gp[eq + 16] = acc[j][0].y;
        gp[eq + 32] = acc[j][1].x;
        gp[eq + 48] = acc[j][1].y;
    }
}

// ---------------- gating finalize: softmax max-prob + argmax -----------------
template<int NSPLIT>
__global__ void gfinal_kernel(const float* __restrict__ GLOG,
                              float scale, int layer) {
    const int t = blockIdx.x;
    const int l = threadIdx.x;
    float v0 = 0.f, v1 = 0.f;
    #pragma unroll
    for (int z = 0; z < NSPLIT; z++) {
        const float* gp = GLOG + ((size_t)z * NTOK + t) * NEXP;
        v0 += gp[l];
        v1 += gp[l + 32];
    }
    v0 *= scale; v1 *= scale;

    float m; int mi;
    if (v0 >= v1) { m = v0; mi = l; } else { m = v1; mi = l + 32; }
    #pragma unroll
    for (int off = 16; off; off >>= 1) {
        float om = __shfl_xor_sync(0xFFFFFFFFu, m, off);
        int omi = __shfl_xor_sync(0xFFFFFFFFu, mi, off);
        if (om > m || (om == m && omi < mi)) { m = om; mi = omi; }
    }
    float s = expf(v0 - m) + expf(v1 - m);
    #pragma unroll
    for (int off = 16; off; off >>= 1)
        s += __shfl_xor_sync(0xFFFFFFFFu, s, off);

    if (l == 0) {
        g_idx[layer][t]  = mi;
        g_gate[layer][t] = 1.0f / s;   // max softmax prob
    }
}

// ---------------- group: histogram + prefix + scatter + tile list ------------
__global__ void group_kernel(int layer) {
    __shared__ int s_cnt[NEXP], s_cur[NEXP];
    const int t = threadIdx.x;
    if (t < NEXP) s_cnt[t] = 0;
    __syncthreads();
    for (int i = t; i < NTOK; i += blockDim.x)
        atomicAdd(&s_cnt[g_idx[layer][i]], 1);
    __syncthreads();
    if (t == 0) {
        int a = 0, nt = 0;
        for (int e = 0; e < NEXP; e++) {
            s_cur[e] = a;
            const int c = s_cnt[e];
            for (int t0 = 0; t0 < c; t0 += 16) {
                int cnt = (c - t0 < 16) ? (c - t0) : 16;
                g_tiles[layer][nt++] = make_int2(e | (cnt << 16), a + t0);
            }
            a += c;
        }
        g_ntile[layer] = nt;
    }
    __syncthreads();
    for (int i = t; i < NTOK; i += blockDim.x) {
        int e = g_idx[layer][i];
        int p = atomicAdd(&s_cur[e], 1);
        g_list[layer][p] = i;
    }
}

// ---------------- FMA micro-block: 4 k-rows x 16 tokens x 4 cols --------------
// One LDS.128 per token feeds 8 FFMA2 (4 rows x 2 col-pairs).
template<int KLEN>
__device__ __forceinline__ void fma_block4(float2 (&acc)[16][2],
                                           const float (&s_x)[16][KLEN],
                                           int kb, const float4 (&wb)[4]) {
    #pragma unroll
    for (int j = 0; j < 16; j++) {
        float4 xa = *(const float4*)&s_x[j][kb];      // broadcast LDS.128
        acc[j][0] = ffma2(make_float2(xa.x, xa.x), make_float2(wb[0].x, wb[0].y), acc[j][0]);
        acc[j][1] = ffma2(make_float2(xa.x, xa.x), make_float2(wb[0].z, wb[0].w), acc[j][1]);
        acc[j][0] = ffma2(make_float2(xa.y, xa.y), make_float2(wb[1].x, wb[1].y), acc[j][0]);
        acc[j][1] = ffma2(make_float2(xa.y, xa.y), make_float2(wb[1].z, wb[1].w), acc[j][1]);
        acc[j][0] = ffma2(make_float2(xa.z, xa.z), make_float2(wb[2].x, wb[2].y), acc[j][0]);
        acc[j][1] = ffma2(make_float2(xa.z, xa.z), make_float2(wb[2].z, wb[2].w), acc[j][1]);
        acc[j][0] = ffma2(make_float2(xa.w, xa.w), make_float2(wb[3].x, wb[3].y), acc[j][0]);
        acc[j][1] = ffma2(make_float2(xa.w, xa.w), make_float2(wb[3].z, wb[3].w), acc[j][1]);
    }
}

// ---------------- grouped expert FC: one 16-token tile per CTA ---------------
// grid = (DOUT/512, 128 slots, DIN/KLEN); 128 threads.
// Warp wg owns cols [blk*512 + wg*128, +128); lane owns 4 cols (LDG.128 W).
// Double-buffered 4-row W batches. Raw partial sums out.
template<int DIN, int DOUT, int KLEN>
__global__ void __launch_bounds__(128, 4)
fc_kernel(const float* __restrict__ X,
          const float* __restrict__ W,
          int layer,
          float* __restrict__ OUT) {
    const int slot = blockIdx.y;
    if (slot >= g_ntile[layer]) return;
    const int2 tile = g_tiles[layer][slot];
    const int e = tile.x & 0xFFFF;
    const int cnt = tile.x >> 16;
    const int tbase = tile.y;

    const int lane = threadIdx.x & 31;
    const int wg = threadIdx.x >> 5;
    const int colBase = blockIdx.x * 512 + wg * 128 + lane * 4;
    const int k0 = blockIdx.z * KLEN;

    __shared__ float s_x[16][KLEN];
    __shared__ int s_row[16];

    const float* Wb = W + (size_t)e * DIN * DOUT + (size_t)k0 * DOUT + colBase;

    // preload both W batches early (hide under X staging)
    float4 wb0[4], wb1[4];
    #pragma unroll
    for (int u = 0; u < 4; u++) wb0[u] = ldcs4(Wb + (size_t)u * DOUT);
    #pragma unroll
    for (int u = 0; u < 4; u++) wb1[u] = ldcs4(Wb + (size_t)(4 + u) * DOUT);

    if (threadIdx.x < 16)
        s_row[threadIdx.x] = (threadIdx.x < cnt)
                             ? g_list[layer][tbase + threadIdx.x] : -1;
    __syncthreads();

    // stage 16 x KLEN chunk of X (float4, coalesced)
    constexpr int K4 = KLEN / 4;
    #pragma unroll
    for (int i = threadIdx.x; i < 16 * K4; i += 128) {
        int t = i / K4, k4 = i % K4;
        int r = s_row[t];
        float4 v = (r >= 0)
            ? *(const float4*)(X + (size_t)r * DIN + k0 + k4 * 4)
            : make_float4(0.f, 0.f, 0.f, 0.f);
        *(float4*)&s_x[t][k4 * 4] = v;
    }
    __syncthreads();

    float2 acc[16][2];
    #pragma unroll
    for (int j = 0; j < 16; j++) {
        acc[j][0] = make_float2(0.f, 0.f);
        acc[j][1] = make_float2(0.f, 0.f);
    }

    #pragma unroll 1
    for (int kb = 0; kb < KLEN; kb += 8) {
        fma_block4<KLEN>(acc, s_x, kb, wb0);
        if (kb + 8 < KLEN) {
            const float* wn = Wb + (size_t)(kb + 8) * DOUT;
            #pragma unroll
            for (int u = 0; u < 4; u++) wb0[u] = ldcs4(wn + (size_t)u * DOUT);
        }
        fma_block4<KLEN>(acc, s_x, kb + 4, wb1);
        if (kb + 12 < KLEN) {
            const float* wn = Wb + (size_t)(kb + 12) * DOUT;
            #pragma unroll
            for (int u = 0; u < 4; u++) wb1[u] = ldcs4(wn + (size_t)u * DOUT);
        }
    }

    // write raw partial sums (per-split slab)
    #pragma unroll
    for (int j = 0; j < 16; j++) {
        int r = s_row[j];
        if (r < 0) continue;
        *(float4*)(OUT + ((size_t)blockIdx.z * NTOK + r) * DOUT + colBase) =
            make_float4(acc[j][0].x, acc[j][0].y, acc[j][1].x, acc[j][1].y);
    }
}

// ---------------- FC1 combine: bias + gate + gelu -> h -----------------------
__global__ void epi1_kernel(const float* __restrict__ B1v,
                            float* __restrict__ H) {
    const int t = blockIdx.x;
    const int c = threadIdx.x * 4;
    const int e = g_idx[0][t];
    const float g = g_gate[0][t];
    float4 s = *(const float4*)(B1v + (size_t)e * HIDV + c);
    #pragma unroll
    for (int z = 0; z < 2; z++) {
        float4 p = *(const float4*)&g_part[((size_t)z * NTOK + t) * HIDV + c];
        s.x += p.x; s.y += p.y; s.z += p.z; s.w += p.w;
    }
    *(float4*)(H + (size_t)t * HIDV + c) =
        make_float4(gelu_f(s.x * g), gelu_f(s.y * g),
                    gelu_f(s.z * g), gelu_f(s.w * g));
}

// ---------------- FC2 combine: bias + gate -> out ----------------------------
__global__ void epi2_kernel(const float* __restrict__ B2v,
                            float* __restrict__ OUT) {
    const int t = blockIdx.x;
    const int c = threadIdx.x * 4;
    const int e = g_idx[1][t];
    const float g = g_gate[1][t];
    float4 s = *(const float4*)(B2v + (size_t)e * DIMV + c);
    #pragma unroll
    for (int z = 0; z < 8; z++) {
        float4 p = *(const float4*)&g_part[((size_t)z * NTOK + t) * DIMV + c];
        s.x += p.x; s.y += p.y; s.z += p.z; s.w += p.w;
    }
    *(float4*)(OUT + (size_t)t * DIMV + c) =
        make_float4(s.x * g, s.y * g, s.z * g, s.w * g);
}

// ---------------- launch ------------------------------------------------------
extern "C" void kernel_launch(void* const* d_in, const int* in_sizes, int n_in,
                              void* d_out, int out_size) {
    const float* x    = (const float*)d_in[0];
    const float* emb1 = (const float*)d_in[1];
    const float* W1   = (const float*)d_in[2];
    const float* b1   = (const float*)d_in[3];
    const float* emb2 = (const float*)d_in[4];
    const float* W2   = (const float*)d_in[5];
    const float* b2   = (const float*)d_in[6];
    float* out = (float*)d_out;

    void* hp = nullptr;
    cudaGetSymbolAddress(&hp, g_h);
    float* h = (float*)hp;
    void* pp = nullptr;
    cudaGetSymbolAddress(&pp, g_part);
    float* part = (float*)pp;
    void* gp = nullptr;
    cudaGetSymbolAddress(&gp, g_glog);
    float* glog = (float*)gp;

    const float scale1 = 0.044194173824159216f;   // 1/sqrt(512)
    const float scale2 = 0.022097086912079612f;   // 1/sqrt(2048)

    // layer-1 gating: tiled logit GEMM (K split x2) + finalize
    glogit_kernel<DIMV, 256><<<dim3(NTOK / 32, 2), 128>>>(x, emb1, glog);
    gfinal_kernel<2><<<NTOK, 32>>>(glog, scale1, 0);
    group_kernel<<<1, 256>>>(0);
    // FC1: K=512 split x2 (KLEN=256), one tile per CTA, 128 tile slots
    fc_kernel<DIMV, HIDV, 256>
        <<<dim3(HIDV / 512, 128, 2), 128>>>(x, W1, 0, part);
    epi1_kernel<<<NTOK, 512>>>(b1, h);

    // layer-2 gating (K split x8)
    glogit_kernel<HIDV, 256><<<dim3(NTOK / 32, 8), 128>>>(h, emb2, glog);
    gfinal_kernel<8><<<NTOK, 32>>>(glog, scale2, 1);
    group_kernel<<<1, 256>>>(1);
    // FC2: K=2048 split x8 (KLEN=256), one tile per CTA
    fc_kernel<HIDV, DIMV, 256>
        <<<dim3(DIMV / 512, 128, 8), 128>>>(h, W2, 1, part);
    epi2_kernel<<<NTOK, 128>>>(b2, out);
}